// round 1
// baseline (speedup 1.0000x reference)
#include <cuda_runtime.h>

// ---------------------------------------------------------------------------
// VariationalQuantumCircuit: 4 qubits, depth 2, batch B.
//
// Math: out_w(x) = psi^T A_w psi, psi = ⊗_w (cos(x_w/2), sin(x_w/2)),
//       A_w = Re(U^H Z_w U) with U the fixed variational unitary.
// Using v v^T = 0.5 (I + cos(x) Z + sin(x) X):
//       out_w = sum_{t in {I,Z,X}^4} K_w[t] * prod_u g_u[t_u],
//       g_u = (1, cos x_u, sin x_u),
//       K_w[t] = (1/16) sum_{i,j} A_w[i,j] prod_u B^{t_u}[i_u, j_u].
// Setup kernel computes K (4 x 81 floats) from q_weights; main kernel does a
// fully-unrolled 81-term contraction per element with packed f32x2 FMAs.
// ---------------------------------------------------------------------------

typedef unsigned long long ull;

__device__ float g_Kraw[81 * 4];   // layout: [t_lin][w], t_lin = ((t3*3+t2)*3+t1)*3+t0

// ---------------- packed f32x2 helpers (Blackwell) -------------------------
__device__ __forceinline__ ull pk2(float v) {
    ull r; asm("mov.b64 %0,{%1,%1};" : "=l"(r) : "f"(v)); return r;
}
__device__ __forceinline__ ull fma2(ull a, ull b, ull c) {
    ull d; asm("fma.rn.f32x2 %0,%1,%2,%3;" : "=l"(d) : "l"(a), "l"(b), "l"(c)); return d;
}
__device__ __forceinline__ float2 unpk(ull v) {
    float2 r; asm("mov.b64 {%0,%1},%2;" : "=f"(r.x), "=f"(r.y) : "l"(v)); return r;
}

// ---------------- complex helpers for setup --------------------------------
__device__ __forceinline__ float2 cmul(float2 a, float2 b) {
    return make_float2(a.x * b.x - a.y * b.y, a.x * b.y + a.y * b.x);
}
__device__ __forceinline__ float2 cadd(float2 a, float2 b) {
    return make_float2(a.x + b.x, a.y + b.y);
}

// ---------------------------------------------------------------------------
// Setup kernel: 1 block, 256 threads. Simulates the fixed part of the circuit
// on the 16 basis states -> U, then A_w = Re(U^H Z_w U), then the K tensor.
// ---------------------------------------------------------------------------
__global__ void vqc_setup_kernel(const float* __restrict__ qw) {
    __shared__ float2 U[16][16];     // U[m][col]
    __shared__ float  A[4][16][16];

    int tid = threadIdx.x;

    // ---- Step 1: columns of U (16 threads each evolve one basis state) ----
    if (tid < 16) {
        float2 st[16];
#pragma unroll
        for (int i = 0; i < 16; i++) st[i] = make_float2(0.f, 0.f);
        st[tid].x = 1.f;

        for (int layer = 0; layer < 2; ++layer) {
            // Rot gates on wires 0..3
            for (int w = 0; w < 4; ++w) {
                float phi = qw[(layer * 4 + w) * 3 + 0];
                float th  = qw[(layer * 4 + w) * 3 + 1];
                float om  = qw[(layer * 4 + w) * 3 + 2];
                float ch = cosf(0.5f * th), sh = sinf(0.5f * th);
                float ca = cosf(0.5f * (phi + om)), sa = sinf(0.5f * (phi + om));
                float cb = cosf(0.5f * (phi - om)), sb = sinf(0.5f * (phi - om));
                // PennyLane Rot = [[e^{-i(phi+om)/2} c, -e^{i(phi-om)/2} s],
                //                  [e^{-i(phi-om)/2} s,  e^{i(phi+om)/2} c]]
                float2 u00 = make_float2( ch * ca, -ch * sa);
                float2 u01 = make_float2(-sh * cb, -sh * sb);
                float2 u10 = make_float2( sh * cb, -sh * sb);
                float2 u11 = make_float2( ch * ca,  ch * sa);
                int mask = 8 >> w;   // wire w <-> bit (3-w)
                for (int i = 0; i < 16; i++) {
                    if (!(i & mask)) {
                        float2 a = st[i], b = st[i | mask];
                        st[i]        = cadd(cmul(u00, a), cmul(u01, b));
                        st[i | mask] = cadd(cmul(u10, a), cmul(u11, b));
                    }
                }
            }
            // CNOTs: (0,1),(1,2),(2,3),(3,0)
            const int ctrls[4] = {0, 1, 2, 3};
            const int tgts[4]  = {1, 2, 3, 0};
            for (int g = 0; g < 4; ++g) {
                int cm = 8 >> ctrls[g], tm = 8 >> tgts[g];
                for (int i = 0; i < 16; i++) {
                    if ((i & cm) && !(i & tm)) {
                        float2 tmp = st[i]; st[i] = st[i | tm]; st[i | tm] = tmp;
                    }
                }
            }
        }
        for (int m = 0; m < 16; m++) U[m][tid] = st[m];
    }
    __syncthreads();

    // ---- Step 2: A[w][i][j] = sum_m z_w(m) Re(conj(U[m,i]) U[m,j]) --------
    {
        int i = tid >> 4, j = tid & 15;
        float aw[4] = {0.f, 0.f, 0.f, 0.f};
        for (int m = 0; m < 16; m++) {
            float re = U[m][i].x * U[m][j].x + U[m][i].y * U[m][j].y;
#pragma unroll
            for (int w = 0; w < 4; w++)
                aw[w] += ((m >> (3 - w)) & 1) ? -re : re;
        }
        for (int w = 0; w < 4; w++) A[w][i][j] = aw[w];
    }
    __syncthreads();

    // ---- Step 3: K tensor: 324 entries ------------------------------------
    for (int idx = tid; idx < 324; idx += 256) {
        int w = idx / 81, t = idx % 81;
        int tt[4];
        tt[0] = t % 3; tt[1] = (t / 3) % 3; tt[2] = (t / 9) % 3; tt[3] = t / 27;
        float k = 0.f;
        for (int i = 0; i < 16; i++) {
            for (int j = 0; j < 16; j++) {
                float prod = A[w][i][j];
#pragma unroll
                for (int u = 0; u < 4; u++) {
                    int bi = (i >> (3 - u)) & 1;
                    int bj = (j >> (3 - u)) & 1;
                    int tu = tt[u];
                    float bval;
                    if (tu == 0)      bval = (bi == bj) ? 1.f : 0.f;          // I
                    else if (tu == 1) bval = (bi == bj) ? (bi ? -1.f : 1.f) : 0.f; // Z
                    else              bval = (bi != bj) ? 1.f : 0.f;          // X
                    prod *= bval;
                }
                k += prod;
            }
        }
        g_Kraw[t * 4 + w] = k * (1.0f / 16.0f);
    }
}

// ---------------------------------------------------------------------------
// Main kernel: one thread per batch element.
// ---------------------------------------------------------------------------
__global__ void __launch_bounds__(256) vqc_main_kernel(
    const float4* __restrict__ x, float4* __restrict__ out, int B) {
    __shared__ float4 Kf[81];
    int tid = threadIdx.x;
    if (tid < 81) Kf[tid] = reinterpret_cast<const float4*>(g_Kraw)[tid];
    __syncthreads();

    int e = blockIdx.x * 256 + tid;
    if (e >= B) return;

    const ulonglong2* K = reinterpret_cast<const ulonglong2*>(Kf);

    float4 xv = x[e];
    float c, s;
    ull C[4], S[4];
    __sincosf(xv.x, &s, &c); C[0] = pk2(c); S[0] = pk2(s);
    __sincosf(xv.y, &s, &c); C[1] = pk2(c); S[1] = pk2(s);
    __sincosf(xv.z, &s, &c); C[2] = pk2(c); S[2] = pk2(s);
    __sincosf(xv.w, &s, &c); C[3] = pk2(c); S[3] = pk2(s);

    ull accA = 0ull, accB = 0ull;   // bits of (0.f,0.f)
#pragma unroll
    for (int t3 = 0; t3 < 3; ++t3) {
        ull t3A = 0ull, t3B = 0ull;
#pragma unroll
        for (int t2 = 0; t2 < 3; ++t2) {
            ull t2A = 0ull, t2B = 0ull;
#pragma unroll
            for (int t1 = 0; t1 < 3; ++t1) {
                int base = ((t3 * 3 + t2) * 3 + t1) * 3;
                ulonglong2 k0 = K[base], k1 = K[base + 1], k2 = K[base + 2];
                // r = K[t0=0] + c0*K[t0=1] + s0*K[t0=2]   (packed over wire pairs)
                ull rA = fma2(C[0], k1.x, k0.x); rA = fma2(S[0], k2.x, rA);
                ull rB = fma2(C[0], k1.y, k0.y); rB = fma2(S[0], k2.y, rB);
                if (t1 == 0)      { t2A = rA;                t2B = rB; }
                else if (t1 == 1) { t2A = fma2(C[1], rA, t2A); t2B = fma2(C[1], rB, t2B); }
                else              { t2A = fma2(S[1], rA, t2A); t2B = fma2(S[1], rB, t2B); }
            }
            if (t2 == 0)      { t3A = t2A;                 t3B = t2B; }
            else if (t2 == 1) { t3A = fma2(C[2], t2A, t3A); t3B = fma2(C[2], t2B, t3B); }
            else              { t3A = fma2(S[2], t2A, t3A); t3B = fma2(S[2], t2B, t3B); }
        }
        if (t3 == 0)      { accA = t3A;                  accB = t3B; }
        else if (t3 == 1) { accA = fma2(C[3], t3A, accA); accB = fma2(C[3], t3B, accB); }
        else              { accA = fma2(S[3], t3A, accA); accB = fma2(S[3], t3B, accB); }
    }

    float2 o01 = unpk(accA);
    float2 o23 = unpk(accB);
    out[e] = make_float4(o01.x, o01.y, o23.x, o23.y);
}

// ---------------------------------------------------------------------------
extern "C" void kernel_launch(void* const* d_in, const int* in_sizes, int n_in,
                              void* d_out, int out_size) {
    const float* x  = (const float*)d_in[0];
    const float* qw = (const float*)d_in[1];
    int sx = in_sizes[0], sq = in_sizes[1];
    if (sx < sq) {  // robustness: q_weights has 24 elements, x has B*4
        const float* t = x; x = qw; qw = t;
        int ts = sx; sx = sq; sq = ts;
    }
    int B = sx / 4;

    vqc_setup_kernel<<<1, 256>>>(qw);
    int grid = (B + 255) / 256;
    vqc_main_kernel<<<grid, 256>>>((const float4*)x, (float4*)d_out, B);
}

// round 4
// speedup vs baseline: 3.2609x; 3.2609x over previous
#include <cuda_runtime.h>

// ---------------------------------------------------------------------------
// VariationalQuantumCircuit: 4 qubits, depth 2, batch B.
//
// out_w = sum_{t in {I,Z,X}^4} K_w[t] * prod_u g_u[t_u],  g_u = (1,cos x_u,sin x_u)
// K_w[t] = (1/16) sum_i (-1)^popc(i & zmask(t)) * A_w[i][i ^ xmask(t)],
// A_w = Re(U^H Z_w U), U = fixed variational unitary from q_weights.
//
// Setup kernel: serial basis-column evolution, fully unrolled (registers).
// Main kernel: 2 batch elements per thread, fully unrolled 81-term contraction
// with packed fma.rn.f32x2 (outputs packed pairwise), K loads reused by both.
// ---------------------------------------------------------------------------

typedef unsigned long long ull;

__device__ float4 g_K4[81];   // K4[t] = (K_w0,K_w1,K_w2,K_w3), t=((t3*3+t2)*3+t1)*3+t0

// ---------------- packed f32x2 helpers (Blackwell) -------------------------
__device__ __forceinline__ ull pk2(float v) {
    ull r; asm("mov.b64 %0,{%1,%1};" : "=l"(r) : "f"(v)); return r;
}
__device__ __forceinline__ ull fma2(ull a, ull b, ull c) {
    ull d; asm("fma.rn.f32x2 %0,%1,%2,%3;" : "=l"(d) : "l"(a), "l"(b), "l"(c)); return d;
}
__device__ __forceinline__ float2 unpk(ull v) {
    float2 r; asm("mov.b64 {%0,%1},%2;" : "=f"(r.x), "=f"(r.y) : "l"(v)); return r;
}

__device__ __forceinline__ float2 cmul(float2 a, float2 b) {
    return make_float2(a.x * b.x - a.y * b.y, a.x * b.y + a.y * b.x);
}
__device__ __forceinline__ float2 cadd(float2 a, float2 b) {
    return make_float2(a.x + b.x, a.y + b.y);
}

// ---------------------------------------------------------------------------
// Setup kernel: 1 block, 256 threads. Step 1 fully unrolled so st[] is
// register-resident (16 threads, one basis column each).
// ---------------------------------------------------------------------------
__global__ void vqc_setup_kernel(const float* __restrict__ qw) {
    __shared__ float2 U[16][16];     // U[m][col]
    __shared__ float  A[4][16][16];

    const int tid = threadIdx.x;

    // ---- Step 1: columns of U (16 threads each evolve one basis state) ----
    if (tid < 16) {
        float2 st[16];
#pragma unroll
        for (int i = 0; i < 16; i++) st[i] = make_float2(0.f, 0.f);
        st[tid].x = 1.f;

#pragma unroll
        for (int layer = 0; layer < 2; ++layer) {
            // Rot gates on wires 0..3
#pragma unroll
            for (int w = 0; w < 4; ++w) {
                float phi = qw[(layer * 4 + w) * 3 + 0];
                float th  = qw[(layer * 4 + w) * 3 + 1];
                float om  = qw[(layer * 4 + w) * 3 + 2];
                float ch = cosf(0.5f * th), sh = sinf(0.5f * th);
                float ca = cosf(0.5f * (phi + om)), sa = sinf(0.5f * (phi + om));
                float cb = cosf(0.5f * (phi - om)), sb = sinf(0.5f * (phi - om));
                // PennyLane Rot = [[e^{-i(phi+om)/2} c, -e^{i(phi-om)/2} s],
                //                  [e^{-i(phi-om)/2} s,  e^{i(phi+om)/2} c]]
                float2 u00 = make_float2( ch * ca, -ch * sa);
                float2 u01 = make_float2(-sh * cb, -sh * sb);
                float2 u10 = make_float2( sh * cb, -sh * sb);
                float2 u11 = make_float2( ch * ca,  ch * sa);
                const int mask = 8 >> w;   // wire w <-> bit (3-w)
#pragma unroll
                for (int i = 0; i < 16; i++) {
                    if (!(i & mask)) {
                        float2 a = st[i], b = st[i | mask];
                        st[i]        = cadd(cmul(u00, a), cmul(u01, b));
                        st[i | mask] = cadd(cmul(u10, a), cmul(u11, b));
                    }
                }
            }
            // CNOTs: (0,1),(1,2),(2,3),(3,0); wire w <-> bit (3-w)
#pragma unroll
            for (int g = 0; g < 4; ++g) {
                const int cm = (g == 0) ? 8 : (g == 1) ? 4 : (g == 2) ? 2 : 1;
                const int tm = (g == 0) ? 4 : (g == 1) ? 2 : (g == 2) ? 1 : 8;
#pragma unroll
                for (int i = 0; i < 16; i++) {
                    if ((i & cm) && !(i & tm)) {
                        float2 tmp = st[i]; st[i] = st[i | tm]; st[i | tm] = tmp;
                    }
                }
            }
        }
#pragma unroll
        for (int m = 0; m < 16; m++) U[m][tid] = st[m];
    }
    __syncthreads();

    // ---- Step 2: A[w][i][j] = sum_m z_w(m) Re(conj(U[m,i]) U[m,j]) --------
    {
        int i = tid >> 4, j = tid & 15;
        float aw[4] = {0.f, 0.f, 0.f, 0.f};
#pragma unroll
        for (int mm = 0; mm < 16; mm++) {
            float re = U[mm][i].x * U[mm][j].x + U[mm][i].y * U[mm][j].y;
#pragma unroll
            for (int w = 0; w < 4; w++)
                aw[w] += ((mm >> (3 - w)) & 1) ? -re : re;
        }
#pragma unroll
        for (int w = 0; w < 4; w++) A[w][i][j] = aw[w];
    }
    __syncthreads();

    // ---- Step 3: K_w[t] = (1/16) sum_i (-1)^popc(i&zmask) A_w[i][i^xmask] -
    // NOTE: stride loop — 324 work items > 256 threads (R2/R3 bug was `if`).
    for (int idx = tid; idx < 324; idx += 256) {
        int w = idx / 81, t = idx % 81;
        int tt[4];
        tt[0] = t % 3; tt[1] = (t / 3) % 3; tt[2] = (t / 9) % 3; tt[3] = t / 27;
        int xmask = 0, zmask = 0;
#pragma unroll
        for (int u = 0; u < 4; u++) {
            int bit = 8 >> u;                  // wire u <-> bit (3-u)
            if (tt[u] == 2) xmask |= bit;      // X
            else if (tt[u] == 1) zmask |= bit; // Z
        }
        float k = 0.f;
#pragma unroll
        for (int i = 0; i < 16; i++) {
            float v = A[w][i][i ^ xmask];
            k += (__popc(i & zmask) & 1) ? -v : v;
        }
        reinterpret_cast<float*>(g_K4)[t * 4 + w] = k * (1.0f / 16.0f);
    }
}

// ---------------------------------------------------------------------------
// Main kernel: 2 batch elements per thread; K loads shared across both.
// ---------------------------------------------------------------------------
__global__ void __launch_bounds__(256) vqc_main_kernel(
    const float4* __restrict__ x, float4* __restrict__ out, int B) {
    __shared__ float4 Kf[81];
    const int tid = threadIdx.x;
    if (tid < 81) Kf[tid] = g_K4[tid];
    __syncthreads();

    const ulonglong2* K = reinterpret_cast<const ulonglong2*>(Kf);

    const int e0 = blockIdx.x * 512 + tid;
    const int e1 = e0 + 256;
    const bool v0 = e0 < B, v1 = e1 < B;

    float4 x0 = v0 ? x[e0] : make_float4(0.f, 0.f, 0.f, 0.f);
    float4 x1 = v1 ? x[e1] : make_float4(0.f, 0.f, 0.f, 0.f);

    float c, s;
    ull C0[4], S0[4], C1[4], S1[4];
    __sincosf(x0.x, &s, &c); C0[0] = pk2(c); S0[0] = pk2(s);
    __sincosf(x0.y, &s, &c); C0[1] = pk2(c); S0[1] = pk2(s);
    __sincosf(x0.z, &s, &c); C0[2] = pk2(c); S0[2] = pk2(s);
    __sincosf(x0.w, &s, &c); C0[3] = pk2(c); S0[3] = pk2(s);
    __sincosf(x1.x, &s, &c); C1[0] = pk2(c); S1[0] = pk2(s);
    __sincosf(x1.y, &s, &c); C1[1] = pk2(c); S1[1] = pk2(s);
    __sincosf(x1.z, &s, &c); C1[2] = pk2(c); S1[2] = pk2(s);
    __sincosf(x1.w, &s, &c); C1[3] = pk2(c); S1[3] = pk2(s);

    ull accA0 = 0ull, accB0 = 0ull, accA1 = 0ull, accB1 = 0ull;
#pragma unroll
    for (int t3 = 0; t3 < 3; ++t3) {
        ull t3A0 = 0ull, t3B0 = 0ull, t3A1 = 0ull, t3B1 = 0ull;
#pragma unroll
        for (int t2 = 0; t2 < 3; ++t2) {
            ull t2A0 = 0ull, t2B0 = 0ull, t2A1 = 0ull, t2B1 = 0ull;
#pragma unroll
            for (int t1 = 0; t1 < 3; ++t1) {
                const int base = ((t3 * 3 + t2) * 3 + t1) * 3;
                ulonglong2 k0 = K[base], k1 = K[base + 1], k2 = K[base + 2];
                // r = K[t0=I] + c0*K[t0=Z] + s0*K[t0=X]  (packed over output pairs)
                ull rA0 = fma2(S0[0], k2.x, fma2(C0[0], k1.x, k0.x));
                ull rB0 = fma2(S0[0], k2.y, fma2(C0[0], k1.y, k0.y));
                ull rA1 = fma2(S1[0], k2.x, fma2(C1[0], k1.x, k0.x));
                ull rB1 = fma2(S1[0], k2.y, fma2(C1[0], k1.y, k0.y));
                if (t1 == 0) {
                    t2A0 = rA0; t2B0 = rB0; t2A1 = rA1; t2B1 = rB1;
                } else if (t1 == 1) {
                    t2A0 = fma2(C0[1], rA0, t2A0); t2B0 = fma2(C0[1], rB0, t2B0);
                    t2A1 = fma2(C1[1], rA1, t2A1); t2B1 = fma2(C1[1], rB1, t2B1);
                } else {
                    t2A0 = fma2(S0[1], rA0, t2A0); t2B0 = fma2(S0[1], rB0, t2B0);
                    t2A1 = fma2(S1[1], rA1, t2A1); t2B1 = fma2(S1[1], rB1, t2B1);
                }
            }
            if (t2 == 0) {
                t3A0 = t2A0; t3B0 = t2B0; t3A1 = t2A1; t3B1 = t2B1;
            } else if (t2 == 1) {
                t3A0 = fma2(C0[2], t2A0, t3A0); t3B0 = fma2(C0[2], t2B0, t3B0);
                t3A1 = fma2(C1[2], t2A1, t3A1); t3B1 = fma2(C1[2], t2B1, t3B1);
            } else {
                t3A0 = fma2(S0[2], t2A0, t3A0); t3B0 = fma2(S0[2], t2B0, t3B0);
                t3A1 = fma2(S1[2], t2A1, t3A1); t3B1 = fma2(S1[2], t2B1, t3B1);
            }
        }
        if (t3 == 0) {
            accA0 = t3A0; accB0 = t3B0; accA1 = t3A1; accB1 = t3B1;
        } else if (t3 == 1) {
            accA0 = fma2(C0[3], t3A0, accA0); accB0 = fma2(C0[3], t3B0, accB0);
            accA1 = fma2(C1[3], t3A1, accA1); accB1 = fma2(C1[3], t3B1, accB1);
        } else {
            accA0 = fma2(S0[3], t3A0, accA0); accB0 = fma2(S0[3], t3B0, accB0);
            accA1 = fma2(S1[3], t3A1, accA1); accB1 = fma2(S1[3], t3B1, accB1);
        }
    }

    if (v0) {
        float2 o01 = unpk(accA0), o23 = unpk(accB0);
        out[e0] = make_float4(o01.x, o01.y, o23.x, o23.y);
    }
    if (v1) {
        float2 o01 = unpk(accA1), o23 = unpk(accB1);
        out[e1] = make_float4(o01.x, o01.y, o23.x, o23.y);
    }
}

// ---------------------------------------------------------------------------
extern "C" void kernel_launch(void* const* d_in, const int* in_sizes, int n_in,
                              void* d_out, int out_size) {
    const float* x  = (const float*)d_in[0];
    const float* qw = (const float*)d_in[1];
    int sx = in_sizes[0], sq = in_sizes[1];
    if (sx < sq) {  // robustness: q_weights has 24 elements, x has B*4
        const float* t = x; x = qw; qw = t;
        int ts = sx; sx = sq; sq = ts;
    }
    int B = sx / 4;

    vqc_setup_kernel<<<1, 256>>>(qw);
    int grid = (B + 511) / 512;
    vqc_main_kernel<<<grid, 256>>>((const float4*)x, (float4*)d_out, B);
}

// round 5
// speedup vs baseline: 3.4649x; 1.0626x over previous
#include <cuda_runtime.h>

// ---------------------------------------------------------------------------
// VariationalQuantumCircuit: 4 qubits, depth 2, batch B.
//
// out_w = sum_{t in {I,Z,X}^4} K_w[t] * prod_u g_u[t_u],  g_u = (1,cos x_u,sin x_u)
// K_w[t] = (1/16) sum_i (-1)^popc(i & zmask(t)) * A_w[i][i ^ xmask(t)],
// A_w = Re(U^H Z_w U), U = fixed variational unitary from q_weights.
//
// Setup kernel: shuffle-parallel basis-column evolution -> U -> A -> K.
// Main kernel: 2 batch elements per thread, fully unrolled 81-term contraction
// with packed fma.rn.f32x2 (outputs packed pairwise), K loads reused by both.
// __launch_bounds__(256,4) caps regs at 64 -> 50% occupancy.
// ---------------------------------------------------------------------------

typedef unsigned long long ull;

__device__ float4 g_K4[81];   // K4[t] = (K_w0,K_w1,K_w2,K_w3), t=((t3*3+t2)*3+t1)*3+t0

// ---------------- packed f32x2 helpers (Blackwell) -------------------------
__device__ __forceinline__ ull pk2(float v) {
    ull r; asm("mov.b64 %0,{%1,%1};" : "=l"(r) : "f"(v)); return r;
}
__device__ __forceinline__ ull fma2(ull a, ull b, ull c) {
    ull d; asm("fma.rn.f32x2 %0,%1,%2,%3;" : "=l"(d) : "l"(a), "l"(b), "l"(c)); return d;
}
__device__ __forceinline__ float2 unpk(ull v) {
    float2 r; asm("mov.b64 {%0,%1},%2;" : "=f"(r.x), "=f"(r.y) : "l"(v)); return r;
}

__device__ __forceinline__ float2 cmul(float2 a, float2 b) {
    return make_float2(a.x * b.x - a.y * b.y, a.x * b.y + a.y * b.x);
}
__device__ __forceinline__ float2 cadd(float2 a, float2 b) {
    return make_float2(a.x + b.x, a.y + b.y);
}

// ---------------------------------------------------------------------------
// Setup kernel: 256 threads = 16 columns x 16 amplitudes, register-resident
// state, gates applied via warp shuffles (shfl distance < 16 stays in-column).
// ---------------------------------------------------------------------------
__global__ void vqc_setup_kernel(const float* __restrict__ qw) {
    __shared__ float2 U[16][16];     // U[m][col]
    __shared__ float  A[4][16][16];

    const int tid = threadIdx.x;
    const int col = tid >> 4;        // basis column (0..15)
    const int m   = tid & 15;        // amplitude index within column

    // ---- Step 1: evolve all 16 basis columns in parallel ------------------
    float2 a = make_float2((m == col) ? 1.f : 0.f, 0.f);

#pragma unroll
    for (int layer = 0; layer < 2; ++layer) {
        // Rot gates on wires 0..3
#pragma unroll
        for (int w = 0; w < 4; ++w) {
            float phi = qw[(layer * 4 + w) * 3 + 0];
            float th  = qw[(layer * 4 + w) * 3 + 1];
            float om  = qw[(layer * 4 + w) * 3 + 2];
            float ch = cosf(0.5f * th), sh = sinf(0.5f * th);
            float ca = cosf(0.5f * (phi + om)), sa = sinf(0.5f * (phi + om));
            float cb = cosf(0.5f * (phi - om)), sb = sinf(0.5f * (phi - om));
            // PennyLane Rot = [[e^{-i(phi+om)/2} c, -e^{i(phi-om)/2} s],
            //                  [e^{-i(phi-om)/2} s,  e^{i(phi+om)/2} c]]
            float2 u00 = make_float2( ch * ca, -ch * sa);
            float2 u01 = make_float2(-sh * cb, -sh * sb);
            float2 u10 = make_float2( sh * cb, -sh * sb);
            float2 u11 = make_float2( ch * ca,  ch * sa);

            const int mask = 8 >> w;   // wire w <-> bit (3-w)
            float bx = __shfl_xor_sync(0xffffffffu, a.x, mask);
            float by = __shfl_xor_sync(0xffffffffu, a.y, mask);
            float2 b = make_float2(bx, by);
            if (m & mask) a = cadd(cmul(u10, b), cmul(u11, a));
            else          a = cadd(cmul(u00, a), cmul(u01, b));
        }
        // CNOTs: (0,1),(1,2),(2,3),(3,0); wire w <-> bit (3-w)
#pragma unroll
        for (int g = 0; g < 4; ++g) {
            const int cm = (g == 0) ? 8 : (g == 1) ? 4 : (g == 2) ? 2 : 1;
            const int tm = (g == 0) ? 4 : (g == 1) ? 2 : (g == 2) ? 1 : 8;
            float bx = __shfl_xor_sync(0xffffffffu, a.x, tm);
            float by = __shfl_xor_sync(0xffffffffu, a.y, tm);
            if (m & cm) { a.x = bx; a.y = by; }
        }
    }
    U[m][col] = a;
    __syncthreads();

    // ---- Step 2: A[w][i][j] = sum_m z_w(m) Re(conj(U[m,i]) U[m,j]) --------
    {
        int i = tid >> 4, j = tid & 15;
        float aw[4] = {0.f, 0.f, 0.f, 0.f};
#pragma unroll
        for (int mm = 0; mm < 16; mm++) {
            float re = U[mm][i].x * U[mm][j].x + U[mm][i].y * U[mm][j].y;
#pragma unroll
            for (int w = 0; w < 4; w++)
                aw[w] += ((mm >> (3 - w)) & 1) ? -re : re;
        }
#pragma unroll
        for (int w = 0; w < 4; w++) A[w][i][j] = aw[w];
    }
    __syncthreads();

    // ---- Step 3: K_w[t] = (1/16) sum_i (-1)^popc(i&zmask) A_w[i][i^xmask] -
    // stride loop — 324 work items > 256 threads
    for (int idx = tid; idx < 324; idx += 256) {
        int w = idx / 81, t = idx % 81;
        int tt[4];
        tt[0] = t % 3; tt[1] = (t / 3) % 3; tt[2] = (t / 9) % 3; tt[3] = t / 27;
        int xmask = 0, zmask = 0;
#pragma unroll
        for (int u = 0; u < 4; u++) {
            int bit = 8 >> u;                  // wire u <-> bit (3-u)
            if (tt[u] == 2) xmask |= bit;      // X
            else if (tt[u] == 1) zmask |= bit; // Z
        }
        float k = 0.f;
#pragma unroll
        for (int i = 0; i < 16; i++) {
            float v = A[w][i][i ^ xmask];
            k += (__popc(i & zmask) & 1) ? -v : v;
        }
        reinterpret_cast<float*>(g_K4)[t * 4 + w] = k * (1.0f / 16.0f);
    }
}

// ---------------------------------------------------------------------------
// Main kernel: 2 batch elements per thread; K loads shared across both.
// ---------------------------------------------------------------------------
__global__ void __launch_bounds__(256, 4) vqc_main_kernel(
    const float4* __restrict__ x, float4* __restrict__ out, int B) {
    __shared__ float4 Kf[81];
    const int tid = threadIdx.x;
    if (tid < 81) Kf[tid] = g_K4[tid];
    __syncthreads();

    const ulonglong2* K = reinterpret_cast<const ulonglong2*>(Kf);

    const int e0 = blockIdx.x * 512 + tid;
    const int e1 = e0 + 256;
    const bool v0 = e0 < B, v1 = e1 < B;

    float4 x0 = v0 ? x[e0] : make_float4(0.f, 0.f, 0.f, 0.f);
    float4 x1 = v1 ? x[e1] : make_float4(0.f, 0.f, 0.f, 0.f);

    float c, s;
    ull C0[4], S0[4], C1[4], S1[4];
    __sincosf(x0.x, &s, &c); C0[0] = pk2(c); S0[0] = pk2(s);
    __sincosf(x0.y, &s, &c); C0[1] = pk2(c); S0[1] = pk2(s);
    __sincosf(x0.z, &s, &c); C0[2] = pk2(c); S0[2] = pk2(s);
    __sincosf(x0.w, &s, &c); C0[3] = pk2(c); S0[3] = pk2(s);
    __sincosf(x1.x, &s, &c); C1[0] = pk2(c); S1[0] = pk2(s);
    __sincosf(x1.y, &s, &c); C1[1] = pk2(c); S1[1] = pk2(s);
    __sincosf(x1.z, &s, &c); C1[2] = pk2(c); S1[2] = pk2(s);
    __sincosf(x1.w, &s, &c); C1[3] = pk2(c); S1[3] = pk2(s);

    ull accA0 = 0ull, accB0 = 0ull, accA1 = 0ull, accB1 = 0ull;
#pragma unroll
    for (int t3 = 0; t3 < 3; ++t3) {
        ull t3A0 = 0ull, t3B0 = 0ull, t3A1 = 0ull, t3B1 = 0ull;
#pragma unroll
        for (int t2 = 0; t2 < 3; ++t2) {
            ull t2A0 = 0ull, t2B0 = 0ull, t2A1 = 0ull, t2B1 = 0ull;
#pragma unroll
            for (int t1 = 0; t1 < 3; ++t1) {
                const int base = ((t3 * 3 + t2) * 3 + t1) * 3;
                ulonglong2 k0 = K[base], k1 = K[base + 1], k2 = K[base + 2];
                // r = K[t0=I] + c0*K[t0=Z] + s0*K[t0=X]  (packed over output pairs)
                ull rA0 = fma2(S0[0], k2.x, fma2(C0[0], k1.x, k0.x));
                ull rB0 = fma2(S0[0], k2.y, fma2(C0[0], k1.y, k0.y));
                ull rA1 = fma2(S1[0], k2.x, fma2(C1[0], k1.x, k0.x));
                ull rB1 = fma2(S1[0], k2.y, fma2(C1[0], k1.y, k0.y));
                if (t1 == 0) {
                    t2A0 = rA0; t2B0 = rB0; t2A1 = rA1; t2B1 = rB1;
                } else if (t1 == 1) {
                    t2A0 = fma2(C0[1], rA0, t2A0); t2B0 = fma2(C0[1], rB0, t2B0);
                    t2A1 = fma2(C1[1], rA1, t2A1); t2B1 = fma2(C1[1], rB1, t2B1);
                } else {
                    t2A0 = fma2(S0[1], rA0, t2A0); t2B0 = fma2(S0[1], rB0, t2B0);
                    t2A1 = fma2(S1[1], rA1, t2A1); t2B1 = fma2(S1[1], rB1, t2B1);
                }
            }
            if (t2 == 0) {
                t3A0 = t2A0; t3B0 = t2B0; t3A1 = t2A1; t3B1 = t2B1;
            } else if (t2 == 1) {
                t3A0 = fma2(C0[2], t2A0, t3A0); t3B0 = fma2(C0[2], t2B0, t3B0);
                t3A1 = fma2(C1[2], t2A1, t3A1); t3B1 = fma2(C1[2], t2B1, t3B1);
            } else {
                t3A0 = fma2(S0[2], t2A0, t3A0); t3B0 = fma2(S0[2], t2B0, t3B0);
                t3A1 = fma2(S1[2], t2A1, t3A1); t3B1 = fma2(S1[2], t2B1, t3B1);
            }
        }
        if (t3 == 0) {
            accA0 = t3A0; accB0 = t3B0; accA1 = t3A1; accB1 = t3B1;
        } else if (t3 == 1) {
            accA0 = fma2(C0[3], t3A0, accA0); accB0 = fma2(C0[3], t3B0, accB0);
            accA1 = fma2(C1[3], t3A1, accA1); accB1 = fma2(C1[3], t3B1, accB1);
        } else {
            accA0 = fma2(S0[3], t3A0, accA0); accB0 = fma2(S0[3], t3B0, accB0);
            accA1 = fma2(S1[3], t3A1, accA1); accB1 = fma2(S1[3], t3B1, accB1);
        }
    }

    if (v0) {
        float2 o01 = unpk(accA0), o23 = unpk(accB0);
        out[e0] = make_float4(o01.x, o01.y, o23.x, o23.y);
    }
    if (v1) {
        float2 o01 = unpk(accA1), o23 = unpk(accB1);
        out[e1] = make_float4(o01.x, o01.y, o23.x, o23.y);
    }
}

// ---------------------------------------------------------------------------
extern "C" void kernel_launch(void* const* d_in, const int* in_sizes, int n_in,
                              void* d_out, int out_size) {
    const float* x  = (const float*)d_in[0];
    const float* qw = (const float*)d_in[1];
    int sx = in_sizes[0], sq = in_sizes[1];
    if (sx < sq) {  // robustness: q_weights has 24 elements, x has B*4
        const float* t = x; x = qw; qw = t;
        int ts = sx; sx = sq; sq = ts;
    }
    int B = sx / 4;

    vqc_setup_kernel<<<1, 256>>>(qw);
    int grid = (B + 511) / 512;
    vqc_main_kernel<<<grid, 256>>>((const float4*)x, (float4*)d_out, B);
}